// round 8
// baseline (speedup 1.0000x reference)
#include <cuda_runtime.h>
#include <cuda_bf16.h>
#include <cstdint>
#include <math.h>

#define NTEST  4096
#define NTRAIN 8192
#define KDIM   1024

#define BM 128          // test rows per CTA
#define BN 128          // train rows per CTA
#define BK 64           // bf16 elements per chunk
#define NCHUNK 48       // 3 segments (hi*hi, hi*lo, lo*hi) x 16 chunks of 64

#define ST_A 0
#define ST_B 16384                 // A stage: 128 rows * 128B
#define STAGE 32768                // + B stage: 128 rows * 128B = 32KB
#define NSTAGE 3
#define SMEM_DYN (NSTAGE * STAGE + 1024)

#define SW(o) ((o) ^ (((o) >> 3) & 0x70))

__device__ __nv_bfloat16 g_Ahi[NTEST  * KDIM];
__device__ __nv_bfloat16 g_Alo[NTEST  * KDIM];
__device__ __nv_bfloat16 g_Bhi[NTRAIN * KDIM];
__device__ __nv_bfloat16 g_Blo[NTRAIN * KDIM];
__device__ float g_labf[NTRAIN];
__device__ float g_S[NTEST * 2];

// ---------------------------------------------------------------------------
__device__ __forceinline__ uint32_t smem_u32(const void* p) {
    uint32_t a;
    asm("{ .reg .u64 t; cvta.to.shared.u64 t, %1; cvt.u32.u64 %0, t; }" : "=r"(a) : "l"(p));
    return a;
}
__device__ __forceinline__ void cp16(uint32_t dst, const void* src) {
    asm volatile("cp.async.cg.shared.global [%0], [%1], 16;" :: "r"(dst), "l"(src));
}
#define CP_COMMIT() asm volatile("cp.async.commit_group;" ::: "memory")
#define CP_WAIT1()  asm volatile("cp.async.wait_group 1;" ::: "memory")

__device__ __forceinline__ void ldsm4(uint32_t& r0, uint32_t& r1, uint32_t& r2,
                                      uint32_t& r3, uint32_t a) {
    asm volatile("ldmatrix.sync.aligned.m8n8.x4.shared.b16 {%0,%1,%2,%3}, [%4];"
                 : "=r"(r0), "=r"(r1), "=r"(r2), "=r"(r3) : "r"(a));
}
__device__ __forceinline__ void mma16816(float* c, const uint32_t* a, const uint32_t* b) {
    asm volatile(
        "mma.sync.aligned.m16n8k16.row.col.f32.bf16.bf16.f32 "
        "{%0,%1,%2,%3}, {%4,%5,%6,%7}, {%8,%9}, {%0,%1,%2,%3};"
        : "+f"(c[0]), "+f"(c[1]), "+f"(c[2]), "+f"(c[3])
        : "r"(a[0]), "r"(a[1]), "r"(a[2]), "r"(a[3]), "r"(b[0]), "r"(b[1]));
}

// ---------------------------------------------------------------------------
// Label prep: detect int64 vs int32 storage, convert to float 0/1.
// ---------------------------------------------------------------------------
__global__ void label_kernel(const int* __restrict__ l32) {
    __shared__ int is64;
    if (threadIdx.x == 0) is64 = 1;
    __syncthreads();
    for (int i = threadIdx.x; i < NTRAIN / 2; i += blockDim.x)
        if (l32[2 * i + 1] != 0) is64 = 0;
    __syncthreads();
    const bool b64 = (is64 != 0);
    for (int i = threadIdx.x; i < NTRAIN; i += blockDim.x)
        g_labf[i] = (float)(b64 ? l32[2 * i] : l32[i]);
}

// ---------------------------------------------------------------------------
// Prep: per-row L2-normalize fp32, split into bf16 hi/lo.
// ---------------------------------------------------------------------------
__global__ __launch_bounds__(256)
void prep_kernel(const float* __restrict__ test, const float* __restrict__ train) {
    const int row = blockIdx.x;
    const float* src;
    __nv_bfloat16 *hi, *lo;
    if (row < NTEST) {
        src = test + (size_t)row * KDIM;
        hi = g_Ahi + (size_t)row * KDIM;
        lo = g_Alo + (size_t)row * KDIM;
    } else {
        int r = row - NTEST;
        src = train + (size_t)r * KDIM;
        hi = g_Bhi + (size_t)r * KDIM;
        lo = g_Blo + (size_t)r * KDIM;
    }
    const int tid = threadIdx.x;
    float4 v = ((const float4*)src)[tid];
    float s = v.x * v.x + v.y * v.y + v.z * v.z + v.w * v.w;
    #pragma unroll
    for (int off = 16; off; off >>= 1) s += __shfl_down_sync(0xFFFFFFFFu, s, off);
    __shared__ float red[8];
    __shared__ float s_inv;
    if ((tid & 31) == 0) red[tid >> 5] = s;
    __syncthreads();
    if (tid == 0) {
        float t = 0.f;
        #pragma unroll
        for (int i = 0; i < 8; i++) t += red[i];
        s_inv = rsqrtf(t);
    }
    __syncthreads();
    const float inv = s_inv;
    float x[4] = {v.x * inv, v.y * inv, v.z * inv, v.w * inv};
    __nv_bfloat16 h[4], l[4];
    #pragma unroll
    for (int i = 0; i < 4; i++) {
        h[i] = __float2bfloat16(x[i]);
        l[i] = __float2bfloat16(x[i] - __bfloat162float(h[i]));
    }
    ((uint2*)hi)[tid] = *(uint2*)h;
    ((uint2*)lo)[tid] = *(uint2*)l;
}

__global__ void zero_kernel() {
    int i = blockIdx.x * blockDim.x + threadIdx.x;
    if (i < NTEST * 2) g_S[i] = 0.f;
}

// ---------------------------------------------------------------------------
// stage loader: chunk c (0..47): seg = c/16 selects hi/lo operands.
// 2048 x 16B over 256 threads.
// ---------------------------------------------------------------------------
__device__ __forceinline__ void load_stage(uint32_t sb, int c, int prow0,
                                           int mcol0, int tid) {
    const __nv_bfloat16* Ag = (c < 32) ? g_Ahi : g_Alo;
    const __nv_bfloat16* Bg = (c < 16) ? g_Bhi : ((c < 32) ? g_Blo : g_Bhi);
    const int k0 = (c & 15) * BK;
    #pragma unroll
    for (int i = tid; i < 2048; i += 256) {
        const __nv_bfloat16* g;
        uint32_t base;
        int row = (i & 1023) >> 3, ch = i & 7;
        if (i < 1024) {
            g = Ag + (size_t)(prow0 + row) * KDIM + k0 + ch * 8;
            base = sb + ST_A;
        } else {
            g = Bg + (size_t)(mcol0 + row) * KDIM + k0 + ch * 8;
            base = sb + ST_B;
        }
        uint32_t off = row * 128 + ch * 16;
        cp16(base + SW(off), g);
    }
    CP_COMMIT();
}

// ---------------------------------------------------------------------------
// Main: bf16 mma.sync hi/lo split GEMM (128x128 tile, 2 CTAs/SM) + PNN epilogue.
// 3-stage cp.async ring, one barrier per chunk, loads issued before compute.
// Every iteration commits exactly one cp.async group (empty at tail) so
// wait_group 1 always proves chunk c's data is resident.
// ---------------------------------------------------------------------------
__global__ __launch_bounds__(256, 2)
void pnn_mma(int dummy) {
    extern __shared__ char dsm[];
    const int tid = threadIdx.x, lane = tid & 31, wid = tid >> 5;
    const int warp_m = wid >> 2, warp_n = wid & 3;   // 2 x 4 warp grid
    const int prow0 = blockIdx.y * BM;
    const int mcol0 = blockIdx.x * BN;

    uint32_t sb0 = (smem_u32(dsm) + 1023u) & ~1023u;
    uint32_t st[NSTAGE] = {sb0, sb0 + STAGE, sb0 + 2 * STAGE};

    float acc[4][4][4];
    #pragma unroll
    for (int mt = 0; mt < 4; mt++)
        #pragma unroll
        for (int nt = 0; nt < 4; nt++)
            #pragma unroll
            for (int k = 0; k < 4; k++) acc[mt][nt][k] = 0.f;

    load_stage(st[0], 0, prow0, mcol0, tid);
    load_stage(st[1], 1, prow0, mcol0, tid);

    int cs = 0;                          // stage index = c % 3
    for (int c = 0; c < NCHUNK; c++) {
        CP_WAIT1();                      // chunk c's group complete
        __syncthreads();                 // visibility + stage (c-1)%3 consumed

        int ls = cs + 2; if (ls >= NSTAGE) ls -= NSTAGE;
        if (c + 2 < NCHUNK) load_stage(st[ls], c + 2, prow0, mcol0, tid);
        else                CP_COMMIT();   // keep one-group-per-iter ledger

        const uint32_t sA = st[cs] + ST_A;
        const uint32_t sB = st[cs] + ST_B;

        #pragma unroll
        for (int s = 0; s < 4; s++) {
            uint32_t a[4][4], b[4][2];
            #pragma unroll
            for (int mt = 0; mt < 4; mt++) {
                int row = warp_m * 64 + mt * 16 + (lane & 15);
                int ch  = 2 * s + (lane >> 4);
                uint32_t off = row * 128 + ch * 16;
                ldsm4(a[mt][0], a[mt][1], a[mt][2], a[mt][3], sA + SW(off));
            }
            #pragma unroll
            for (int bt = 0; bt < 2; bt++) {
                int row = warp_n * 32 + bt * 16 + (lane & 7) + ((lane >> 4) << 3);
                int ch  = 2 * s + ((lane >> 3) & 1);
                uint32_t off = row * 128 + ch * 16;
                ldsm4(b[2 * bt][0], b[2 * bt][1], b[2 * bt + 1][0], b[2 * bt + 1][1],
                      sB + SW(off));
            }
            #pragma unroll
            for (int mt = 0; mt < 4; mt++)
                #pragma unroll
                for (int nt = 0; nt < 4; nt++)
                    mma16816(acc[mt][nt], a[mt], b[nt]);
        }

        if (++cs >= NSTAGE) cs = 0;
    }
    __syncthreads();   // all warps done with smem before epilogue reuse

    // ---- epilogue: smem now reusable ----
    float* labf_s = (float*)dsm;              // 128 labels (512B)
    float* sS     = (float*)(dsm + 2048);     // 128 rows x 2 classes
    if (tid < BN) labf_s[tid] = g_labf[mcol0 + tid];
    sS[tid] = 0.f;                            // 256 entries, 256 threads
    __syncthreads();

    #pragma unroll
    for (int mt = 0; mt < 4; mt++) {
        float r0s0 = 0.f, r0s1 = 0.f, r1s0 = 0.f, r1s1 = 0.f;
        #pragma unroll
        for (int nt = 0; nt < 4; nt++) {
            #pragma unroll
            for (int k = 0; k < 4; k++) {
                int cn = warp_n * 32 + nt * 8 + 2 * (lane & 3) + (k & 1);
                float s  = acc[mt][nt][k];
                float d2 = fmaxf(2.f - 2.f * s, 0.f);
                float sq;
                asm("sqrt.approx.f32 %0, %1;" : "=f"(sq) : "f"(d2));
                float g  = __expf(-2.f * sq);
                float lb = labf_s[cn];
                if (k < 2) { r0s0 += g; r0s1 += g * lb; }
                else       { r1s0 += g; r1s1 += g * lb; }
            }
        }
        r0s0 -= r0s1; r1s0 -= r1s1;
        #pragma unroll
        for (int off = 1; off < 4; off <<= 1) {
            r0s0 += __shfl_xor_sync(0xFFFFFFFFu, r0s0, off);
            r0s1 += __shfl_xor_sync(0xFFFFFFFFu, r0s1, off);
            r1s0 += __shfl_xor_sync(0xFFFFFFFFu, r1s0, off);
            r1s1 += __shfl_xor_sync(0xFFFFFFFFu, r1s1, off);
        }
        if ((lane & 3) == 0) {
            int rl = warp_m * 64 + mt * 16 + (lane >> 2);
            atomicAdd(&sS[2 * rl + 0], r0s0);
            atomicAdd(&sS[2 * rl + 1], r0s1);
            atomicAdd(&sS[2 * (rl + 8) + 0], r1s0);
            atomicAdd(&sS[2 * (rl + 8) + 1], r1s1);
        }
    }
    __syncthreads();
    atomicAdd(&g_S[2 * prow0 + tid], sS[tid]);
}

// ---------------------------------------------------------------------------
__global__ void finalize_kernel(float* __restrict__ out, int out_size) {
    int p = blockIdx.x * blockDim.x + threadIdx.x;
    if (p >= NTEST) return;
    float s0 = g_S[2 * p], s1 = g_S[2 * p + 1];
    float p0 = s0 / (s0 + s1);
    float p1 = s1 / (s0 + s1);
    float res = (s1 > s0) ? 1.f : 0.f;
    if (out_size >= NTEST * 3) {
        out[p] = res;
        out[NTEST + 2 * p]     = p0;
        out[NTEST + 2 * p + 1] = p1;
    } else if (out_size == NTEST * 2) {
        out[2 * p]     = p0;
        out[2 * p + 1] = p1;
    } else {
        if (p < out_size) out[p] = res;
    }
}

// ---------------------------------------------------------------------------
extern "C" void kernel_launch(void* const* d_in, const int* in_sizes, int n_in,
                              void* d_out, int out_size) {
    const float* train = nullptr;
    const float* test  = nullptr;
    const int*   label = nullptr;
    for (int i = 0; i < n_in; i++) {
        if (in_sizes[i] == NTRAIN * KDIM)      train = (const float*)d_in[i];
        else if (in_sizes[i] == NTEST * KDIM)  test  = (const float*)d_in[i];
        else if (in_sizes[i] == NTRAIN)        label = (const int*)d_in[i];
    }

    cudaFuncSetAttribute(pnn_mma, cudaFuncAttributeMaxDynamicSharedMemorySize, SMEM_DYN);

    label_kernel<<<1, 1024>>>(label);
    prep_kernel<<<NTEST + NTRAIN, 256>>>(test, train);
    zero_kernel<<<(NTEST * 2 + 255) / 256, 256>>>();

    dim3 grid(NTRAIN / BN, NTEST / BM);   // (64, 32) = 2048 CTAs
    pnn_mma<<<grid, 256, SMEM_DYN>>>(0);

    finalize_kernel<<<(NTEST + 255) / 256, 256>>>((float*)d_out, out_size);
}